// round 16
// baseline (speedup 1.0000x reference)
#include <cuda_runtime.h>
#include <math.h>
#include <stdint.h>

// ---------------- problem constants ----------------
#define BB   8
#define MM   1024
#define DD   768
#define NE   32
#define PE   32
#define KK   8
#define HH   2048
#define SS   1024            // N*P
#define TT   8192            // B*M
#define NG   256             // token groups for segment stats
#define STAGES 3
#define NCAND 16

// ---------------- scratch (device globals; no allocs allowed) ----------------
__device__ float g_xn   [TT * DD];
__device__ float g_xnw  [TT * DD];          // xn * W[ca] (full precision: rescore)
__device__ float g_colinv[SS];
__device__ float g_phinT[SS * DD];          // full-precision phi*colinv, slot-major
__device__ float g_part [NG * NE * DD];
__device__ float g_part2[NG * NE * DD];
__device__ int   g_icnt [NE];
__device__ float g_mean [NE * DD];
__device__ float g_mad  [NE * DD];
__device__ float g_W    [NE * DD];
__device__ float g_E    [TT * SS];          // tf32(exp(logits))  — logits never stored
__device__ int   g_cand [TT * NCAND];
__device__ float g_rowsum[TT];              // 1 / sum_s E
__device__ float g_colsum[BB * SS];         // 1 / sum_m E
__device__ float g_xs [NE * (BB*PE) * DD];  // combined, tf32-rounded
__device__ float g_h  [NE * (BB*PE) * HH];  // tf32-rounded
__device__ float g_ys [NE * (BB*PE) * DD];  // combined, tf32-rounded
__device__ float g_xsp[2][NE * (BB*PE) * DD];   // split-K partials
__device__ float g_ysp[2][NE * (BB*PE) * DD];
__device__ float g_yp [2][TT * DD];

__device__ __forceinline__ float gelu_f(float v) {
    return 0.5f * v * (1.0f + erff(v * 0.70710678118654752440f));
}

__device__ __forceinline__ float tf32r(float x) {
    uint32_t r;
    asm("cvt.rna.tf32.f32 %0, %1;" : "=r"(r) : "f"(x));
    return __uint_as_float(r);
}

__device__ __forceinline__ void mma_tf32(float* c, const uint32_t* a,
                                         uint32_t b0, uint32_t b1) {
    asm volatile(
        "mma.sync.aligned.m16n8k8.row.col.f32.tf32.tf32.f32 "
        "{%0,%1,%2,%3}, {%4,%5,%6,%7}, {%8,%9}, {%0,%1,%2,%3};"
        : "+f"(c[0]), "+f"(c[1]), "+f"(c[2]), "+f"(c[3])
        : "r"(a[0]), "r"(a[1]), "r"(a[2]), "r"(a[3]), "r"(b0), "r"(b1));
}

__device__ __forceinline__ void cpasync16(uint32_t dst, const void* src) {
    asm volatile("cp.async.ca.shared.global [%0], [%1], 16;" :: "r"(dst), "l"(src));
}
#define CP_COMMIT()  asm volatile("cp.async.commit_group;" ::: "memory")
#define CP_WAIT1()   asm volatile("cp.async.wait_group 1;"  ::: "memory")

// ---------------- parallel colinv (+ zero cluster counts) ----------------
__global__ void k_colinv(const float* __restrict__ phi, const float* __restrict__ scale) {
    int c = blockIdx.x * 32 + (threadIdx.x & 31);
    int rr = threadIdx.x >> 5;
    if (blockIdx.x == 0 && threadIdx.x < NE) g_icnt[threadIdx.x] = 0;
    float ss = 0.f;
    for (int d = rr; d < DD; d += 8) {
        float v = phi[(size_t)d * SS + c];
        ss += v * v;
    }
    __shared__ float ps[8][33];
    ps[rr][threadIdx.x & 31] = ss;
    __syncthreads();
    if (rr == 0) {
        float v = 0.f;
        #pragma unroll
        for (int r = 0; r < 8; r++) v += ps[r][threadIdx.x & 31];
        g_colinv[c] = scale[0] / fmaxf(sqrtf(v), 1e-12f);
    }
}

// ---------------- phinT = (phi * colinv)^T ----------------
__global__ void k_phinT(const float* __restrict__ phi) {
    __shared__ float tile[32][33];
    int s0 = blockIdx.x * 32, d0 = blockIdx.y * 32;
    int lane = threadIdx.x & 31, w = threadIdx.x >> 5;
    #pragma unroll
    for (int r = w; r < 32; r += 8)
        tile[r][lane] = phi[(size_t)(d0 + r) * SS + s0 + lane];
    __syncthreads();
    #pragma unroll
    for (int r = w; r < 32; r += 8) {
        int s = s0 + r;
        g_phinT[(size_t)s * DD + d0 + lane] = tile[lane][r] * g_colinv[s];
    }
}

// ---------------- token L2 normalize ----------------
__global__ void k_norm_x(const float* __restrict__ x) {
    int t = blockIdx.x, tid = threadIdx.x;
    const float* xr = x + (size_t)t * DD;
    float v0 = xr[tid], v1 = xr[tid + 256], v2 = xr[tid + 512];
    __shared__ float red[256];
    red[tid] = v0*v0 + v1*v1 + v2*v2;
    __syncthreads();
    for (int o = 128; o; o >>= 1) { if (tid < o) red[tid] += red[tid+o]; __syncthreads(); }
    float inv = 1.0f / fmaxf(sqrtf(red[0]), 1e-12f);
    float* o = g_xn + (size_t)t * DD;
    o[tid] = v0*inv; o[tid+256] = v1*inv; o[tid+512] = v2*inv;
}

// ---------------- ACMoE segment stats (deterministic) ----------------
__global__ void k_seg0(const int* __restrict__ ca) {
    __shared__ float acc[NE][129];
    __shared__ int cs[32];
    int tid = threadIdx.x;
    int tg = blockIdx.x, d0 = blockIdx.y * 128;
    #pragma unroll
    for (int c = 0; c < NE; c++) acc[c][tid] = 0.f;
    if (tid < 32) {
        cs[tid] = ca[(size_t)(tg * 32 + tid) * KK];
        if (blockIdx.y == 0) atomicAdd(&g_icnt[cs[tid]], 1);
    }
    __syncthreads();
    const float* base = g_xn + (size_t)(tg * 32) * DD + d0 + tid;
    #pragma unroll 4
    for (int tt = 0; tt < 32; tt++)
        acc[cs[tt]][tid] += base[(size_t)tt * DD];
    __syncthreads();
    #pragma unroll
    for (int c = 0; c < NE; c++)
        g_part[((size_t)tg * NE + c) * DD + d0 + tid] = acc[c][tid];
}

__global__ void k_red_mean() {
    int i = blockIdx.x * 256 + threadIdx.x;
    if (i >= NE * DD) return;
    float s = 0.f;
    #pragma unroll 8
    for (int g = 0; g < NG; g++) s += g_part[(size_t)g * NE * DD + i];
    float cn = (float)g_icnt[i / DD];
    g_mean[i] = cn > 0.f ? s / cn : 0.f;
}

__global__ void k_seg1(const int* __restrict__ ca) {
    __shared__ float acc[NE][129];
    __shared__ float meanS[NE][129];
    __shared__ int cs[32];
    int tid = threadIdx.x;
    int tg = blockIdx.x, d0 = blockIdx.y * 128;
    #pragma unroll
    for (int c = 0; c < NE; c++) {
        acc[c][tid] = 0.f;
        meanS[c][tid] = g_mean[c * DD + d0 + tid];
    }
    if (tid < 32) cs[tid] = ca[(size_t)(tg * 32 + tid) * KK];
    __syncthreads();
    const float* base = g_xn + (size_t)(tg * 32) * DD + d0 + tid;
    #pragma unroll 4
    for (int tt = 0; tt < 32; tt++) {
        int c = cs[tt];
        acc[c][tid] += fabsf(base[(size_t)tt * DD] - meanS[c][tid]);
    }
    __syncthreads();
    #pragma unroll
    for (int c = 0; c < NE; c++)
        g_part2[((size_t)tg * NE + c) * DD + d0 + tid] = acc[c][tid];
}

__global__ void k_red_mad() {
    int i = blockIdx.x * 256 + threadIdx.x;
    if (i >= NE * DD) return;
    float s = 0.f;
    #pragma unroll 8
    for (int g = 0; g < NG; g++) s += g_part2[(size_t)g * NE * DD + i];
    float cn = (float)g_icnt[i / DD];
    g_mad[i] = cn > 0.f ? s / cn : 0.f;
}

__global__ void k_W() {
    __shared__ float red[1024];
    int tid = threadIdx.x;
    float l = 0.f;
    for (int i = tid; i < NE * DD; i += 1024) l += 1.0f / (g_mad[i] + 0.35f);
    red[tid] = l; __syncthreads();
    for (int o = 512; o; o >>= 1) { if (tid < o) red[tid] += red[tid+o]; __syncthreads(); }
    float top = 5.0f * red[0] / (float)(NE * DD);
    __syncthreads();
    float l2 = 0.f;
    for (int i = tid; i < NE * DD; i += 1024) l2 += fminf(1.0f / (g_mad[i] + 0.35f), top);
    red[tid] = l2; __syncthreads();
    for (int o = 512; o; o >>= 1) { if (tid < o) red[tid] += red[tid+o]; __syncthreads(); }
    float m2 = red[0] / (float)(NE * DD);
    __syncthreads();
    for (int i = tid; i < NE * DD; i += 1024)
        g_W[i] = fminf(1.0f / (g_mad[i] + 0.35f), top) / m2;
}

__global__ void k_apply(const int* __restrict__ ca) {
    int t = blockIdx.x, tid = threadIdx.x;
    int c = ca[(size_t)t * KK];
    const float* Wr = g_W + (size_t)c * DD;
    const float* xr = g_xn + (size_t)t * DD;
    float* o = g_xnw + (size_t)t * DD;
    o[tid]       = xr[tid]       * Wr[tid];
    o[tid + 256] = xr[tid + 256] * Wr[tid + 256];
    o[tid + 512] = xr[tid + 512] * Wr[tid + 512];
}

// ---------------- unified tf32 tensor-core GEMM, cp.async 3-stage, BN=128 ----------------
// MODE0: E = tf32(exp(xnw @ (phi*colinv)))  single tf32, E-only output
// MODE1: xs partial (split-K x2): E^T @ xnw   -> g_xsp[half]  (raw)
// MODE2: h  = tf32(gelu(xs @ w1 + b1))
// MODE3: ys partial (split-K x2): h @ w2      -> g_ysp[half]  (raw)
// MODE4: y  partial (split-K x2): E @ ys_gath -> g_yp[half]   (raw)
template<int MODE>
__global__ void __launch_bounds__(256, 2) gemm_tc(const float* __restrict__ Bext,
                                                   const float* __restrict__ biasext,
                                                   float* __restrict__ Cext,
                                                   const int* __restrict__ ca) {
    constexpr int KD = (MODE==0)?768 : (MODE==1)?512 : (MODE==2)?768 : (MODE==3)?1024 : 512;
    constexpr int BK = 16;
    constexpr int NT = KD / BK;
    constexpr bool AKMAJ = (MODE==1);
    constexpr bool ACVT  = (MODE==0);
    constexpr bool BCVT  = (MODE==1) || (MODE==2) || (MODE==3);
    constexpr bool BSTAGEREG = (MODE==0);
    constexpr bool SPLITK = (MODE==1) || (MODE==3) || (MODE==4);
    constexpr int ASZ = AKMAJ ? 16*136 : 128*20;
    constexpr int BSZ = 16*136;

    const int zz = blockIdx.z;
    const int z    = SPLITK ? (zz >> 1) : zz;     // batch or expert
    const int half = SPLITK ? (zz & 1) : 0;
    const int i0 = blockIdx.y * 128, j0 = blockIdx.x * 128;
    const int tid = threadIdx.x, lane = tid & 31, warp = tid >> 5;
    const int wmi = warp & 3, wni = warp >> 2;

    extern __shared__ float smem[];
    float* Asm = smem;
    float* Bsm = smem + STAGES * ASZ;
    const uint32_t As_u = (uint32_t)__cvta_generic_to_shared(Asm);
    const uint32_t Bs_u = (uint32_t)__cvta_generic_to_shared(Bsm);

    const float* Aptr = nullptr; int lda = 0;
    const float* Bptr = nullptr; int ldb = 0;
    if constexpr (MODE==0) { Aptr = g_xnw;  lda = 768;  Bptr = Bext; ldb = 1024; }  // raw phi
    if constexpr (MODE==1) { Aptr = g_E + (size_t)z*1024*1024 + (size_t)half*512*1024;   // k-major
                             Bptr = g_xnw + (size_t)z*1024*768 + (size_t)half*512*768; ldb = 768; }
    if constexpr (MODE==2) { Aptr = g_xs + (size_t)z*256*768;   lda = 768;
                             Bptr = Bext + (size_t)z*768*2048;  ldb = 2048; }
    if constexpr (MODE==3) { Aptr = g_h  + (size_t)z*256*2048 + half*1024; lda = 2048;
                             Bptr = Bext + (size_t)z*2048*768 + (size_t)half*1024*768; ldb = 768; }
    if constexpr (MODE==4) { Aptr = g_E + (size_t)z*1024*1024 + half*512; lda = 1024;
                             Bptr = g_ys; ldb = 768; }

    const int akk = tid >> 4, ac = (tid & 15) * 8;   // register-staged B indices (MODE0)
    float ci[8];
    if constexpr (BSTAGEREG) {
        #pragma unroll
        for (int q = 0; q < 8; q++) ci[q] = g_colinv[j0 + ac + q];
    }

    float acc[2][8][4];
    #pragma unroll
    for (int mf = 0; mf < 2; mf++)
        #pragma unroll
        for (int nf = 0; nf < 8; nf++)
            #pragma unroll
            for (int q = 0; q < 4; q++) acc[mf][nf][q] = 0.f;

    float4 rb0, rb1;

    auto issue = [&](int it) {
        const int k0 = it * BK;
        const int st = it % STAGES;
        #pragma unroll
        for (int q = 0; q < 2; q++) {
            int c = tid + q * 256;
            if constexpr (AKMAJ) {
                int kk = c >> 5, col = (c & 31) * 4;
                cpasync16(As_u + (uint32_t)(st*ASZ + kk*136 + col) * 4,
                          Aptr + (size_t)(k0 + kk) * 1024 + i0 + col);
            } else {
                int row = c >> 2, col = (c & 3) * 4;
                cpasync16(As_u + (uint32_t)(st*ASZ + row*20 + col) * 4,
                          Aptr + (size_t)(i0 + row) * lda + k0 + col);
            }
        }
        if constexpr (!BSTAGEREG) {
            #pragma unroll
            for (int q = 0; q < 2; q++) {
                int c = tid + q * 256;
                int kk = c >> 5, col = (c & 31) * 4;
                const float* src;
                if constexpr (MODE==4) {
                    int s = half * 512 + k0 + kk;
                    src = Bptr + (size_t)((s >> 5) * 256 + z * 32 + (s & 31)) * 768 + j0 + col;
                } else {
                    src = Bptr + (size_t)(k0 + kk) * ldb + j0 + col;
                }
                cpasync16(Bs_u + (uint32_t)(st*BSZ + kk*136 + col) * 4, src);
            }
        }
    };

    auto loadB0 = [&](int it) {
        const int k0 = it * BK;
        const float* p = Bptr + (size_t)(k0 + akk) * ldb + j0 + ac;
        rb0 = *(const float4*)p;
        rb1 = *(const float4*)(p + 4);
    };
    auto stageB0 = [&](int st) {
        float* d = &Bsm[st*BSZ + akk*136 + ac];
        d[0] = tf32r(rb0.x*ci[0]); d[1] = tf32r(rb0.y*ci[1]);
        d[2] = tf32r(rb0.z*ci[2]); d[3] = tf32r(rb0.w*ci[3]);
        d[4] = tf32r(rb1.x*ci[4]); d[5] = tf32r(rb1.y*ci[5]);
        d[6] = tf32r(rb1.z*ci[6]); d[7] = tf32r(rb1.w*ci[7]);
    };

    auto compute = [&](int st) {
        const float* A = Asm + st * ASZ;
        const float* B = Bsm + st * BSZ;
        #pragma unroll
        for (int ks = 0; ks < 2; ks++) {
            const int kq = ks * 8 + (lane & 3);
            const int rbase = wmi * 32 + (lane >> 2);
            float ar[2][4];
            #pragma unroll
            for (int mf = 0; mf < 2; mf++) {
                if constexpr (AKMAJ) {
                    ar[mf][0] = A[kq*136     + rbase + mf*16];
                    ar[mf][1] = A[kq*136     + rbase + mf*16 + 8];
                    ar[mf][2] = A[(kq+4)*136 + rbase + mf*16];
                    ar[mf][3] = A[(kq+4)*136 + rbase + mf*16 + 8];
                } else {
                    ar[mf][0] = A[(rbase + mf*16    )*20 + kq];
                    ar[mf][1] = A[(rbase + mf*16 + 8)*20 + kq];
                    ar[mf][2] = A[(rbase + mf*16    )*20 + kq + 4];
                    ar[mf][3] = A[(rbase + mf*16 + 8)*20 + kq + 4];
                }
            }
            uint32_t ahi[2][4];
            #pragma unroll
            for (int mf = 0; mf < 2; mf++)
                #pragma unroll
                for (int q = 0; q < 4; q++) {
                    if constexpr (ACVT) ahi[mf][q] = __float_as_uint(tf32r(ar[mf][q]));
                    else                ahi[mf][q] = __float_as_uint(ar[mf][q]);
                }
            #pragma unroll
            for (int nf = 0; nf < 8; nf++) {
                const int nidx = wni * 64 + nf * 8 + (lane >> 2);
                float b0r = B[kq*136 + nidx];
                float b1r = B[(kq+4)*136 + nidx];
                uint32_t bh0, bh1;
                if constexpr (BCVT) {
                    bh0 = __float_as_uint(tf32r(b0r));
                    bh1 = __float_as_uint(tf32r(b1r));
                } else {
                    bh0 = __float_as_uint(b0r);
                    bh1 = __float_as_uint(b1r);
                }
                mma_tf32(acc[0][nf], ahi[0], bh0, bh1);
                mma_tf32(acc[1][nf], ahi[1], bh0, bh1);
            }
        }
    };

    if constexpr (BSTAGEREG) {
        loadB0(0); stageB0(0);
        issue(0); CP_COMMIT();
        loadB0(1); stageB0(1);
        issue(1); CP_COMMIT();
        for (int it = 0; it < NT; it++) {
            const int buf = it % STAGES;
            CP_WAIT1();
            __syncthreads();
            if (it + 2 < NT) loadB0(it + 2);
            compute(buf);
            if (it + 2 < NT) { stageB0((it + 2) % STAGES); issue(it + 2); }
            CP_COMMIT();
        }
    } else {
        issue(0); CP_COMMIT();
        issue(1); CP_COMMIT();
        for (int it = 0; it < NT; it++) {
            const int buf = it % STAGES;
            CP_WAIT1();
            __syncthreads();
            compute(buf);
            if (it + 2 < NT) issue(it + 2);
            CP_COMMIT();
        }
    }

    // epilogue
    #pragma unroll
    for (int mf = 0; mf < 2; mf++) {
        const int r0 = i0 + wmi * 32 + mf * 16 + (lane >> 2);
        #pragma unroll
        for (int nf = 0; nf < 8; nf++) {
            const int c = j0 + wni * 64 + nf * 8 + (lane & 3) * 2;
            float v00 = acc[mf][nf][0], v01 = acc[mf][nf][1];
            float v10 = acc[mf][nf][2], v11 = acc[mf][nf][3];
            if constexpr (MODE==2) {
                const float* bp = biasext + (size_t)z * 2048 + c;
                float bx = bp[0], by = bp[1];
                v00 = tf32r(gelu_f(v00 + bx)); v01 = tf32r(gelu_f(v01 + by));
                v10 = tf32r(gelu_f(v10 + bx)); v11 = tf32r(gelu_f(v11 + by));
            }
            float* o0; float* o1;
            if constexpr (MODE==0) {
                size_t off0 = (size_t)r0 * SS + c;
                size_t off1 = off0 + (size_t)8 * SS;
                float2 e0 = {tf32r(__expf(v00)), tf32r(__expf(v01))};
                float2 e1 = {tf32r(__expf(v10)), tf32r(__expf(v11))};
                *(float2*)(g_E + off0) = e0;
                *(float2*)(g_E + off1) = e1;
                continue;
            }
            if constexpr (MODE==1) {   // raw partial, scatter layout
                int rr0 = r0, rr1 = r0 + 8;
                o0 = g_xsp[half] + (size_t)((rr0 >> 5) * 256 + z * 32 + (rr0 & 31)) * 768 + c;
                o1 = g_xsp[half] + (size_t)((rr1 >> 5) * 256 + z * 32 + (rr1 & 31)) * 768 + c;
            }
            if constexpr (MODE==2) {
                o0 = g_h + (size_t)z*256*2048 + (size_t)r0 * 2048 + c;
                o1 = o0 + (size_t)8 * 2048;
            }
            if constexpr (MODE==3) {   // raw partial
                o0 = g_ysp[half] + (size_t)z*256*768 + (size_t)r0 * 768 + c;
                o1 = o0 + (size_t)8 * 768;
            }
            if constexpr (MODE==4) {   // raw partial
                o0 = g_yp[half] + (size_t)z*1024*768 + (size_t)r0 * 768 + c;
                o1 = o0 + (size_t)8 * 768;
            }
            float2 w0 = {v00, v01}, w1 = {v10, v11};
            *(float2*)o0 = w0;
            *(float2*)o1 = w1;
        }
    }
}

// ---------------- split-K combines (deterministic fixed-order adds) ----------------
__global__ void k_comb_xs() {
    int rr = blockIdx.x;                   // 0..8191 rows of xs [n][b*32+p]
    int n = rr >> 8, r = rr & 255;
    int b = r >> 5, p = r & 31;
    float sc = g_colsum[b * SS + n * 32 + p];
    const float* p0 = g_xsp[0] + (size_t)rr * DD;
    const float* p1 = g_xsp[1] + (size_t)rr * DD;
    float* o = g_xs + (size_t)rr * DD;
    for (int d = threadIdx.x; d < DD; d += 256)
        o[d] = tf32r((p0[d] + p1[d]) * sc);
}

__global__ void k_comb_ys(const float* __restrict__ b2) {
    int rr = blockIdx.x;                   // 0..8191 rows of ys [n][row]
    int e = rr >> 8;
    const float* p0 = g_ysp[0] + (size_t)rr * DD;
    const float* p1 = g_ysp[1] + (size_t)rr * DD;
    const float* bp = b2 + (size_t)e * DD;
    float* o = g_ys + (size_t)rr * DD;
    for (int d = threadIdx.x; d < DD; d += 256)
        o[d] = tf32r(p0[d] + p1[d] + bp[d]);
}

__global__ void k_comb_y(float* __restrict__ out) {
    int rr = blockIdx.x;                   // token 0..8191
    float sc = g_rowsum[rr];
    const float* p0 = g_yp[0] + (size_t)rr * DD;
    const float* p1 = g_yp[1] + (size_t)rr * DD;
    float* o = out + (size_t)rr * DD;
    for (int d = threadIdx.x; d < DD; d += 256)
        o[d] = (p0[d] + p1[d]) * sc;
}

// ---------------- merged stats: top-16 candidates on E + 1/rowsum + 1/colsum ----------------
__global__ void k_stats() {
    if (blockIdx.x < 1024) {
        int warp = threadIdx.x >> 5, lane = threadIdx.x & 31;
        int row = blockIdx.x * 8 + warp;
        const float* L = g_E + (size_t)row * SS;   // E is monotone in logit
        float v[32];
        #pragma unroll
        for (int j = 0; j < 32; j++) v[j] = L[j * 32 + lane];
        float lastv = INFINITY; int lasti = -1;
        #pragma unroll
        for (int sel = 0; sel < NCAND; sel++) {
            float bv = -INFINITY; int bi = 1 << 30;
            #pragma unroll
            for (int j = 0; j < 32; j++) {
                int gi = j * 32 + lane;
                float val = v[j];
                bool elig   = (val < lastv) || ((val == lastv) && (gi > lasti));
                bool better = (val > bv)    || ((val == bv)    && (gi < bi));
                if (elig && better) { bv = val; bi = gi; }
            }
            for (int o = 16; o; o >>= 1) {
                float ov = __shfl_xor_sync(0xffffffff, bv, o);
                int   oi = __shfl_xor_sync(0xffffffff, bi, o);
                if ((ov > bv) || ((ov == bv) && (oi < bi))) { bv = ov; bi = oi; }
            }
            lastv = bv; lasti = bi;
            if (lane == 0) g_cand[(size_t)row * NCAND + sel] = bi;
        }
        float sm = 0.f;
        #pragma unroll
        for (int j = 0; j < 32; j++) sm += v[j];
        for (int o = 16; o; o >>= 1) sm += __shfl_xor_sync(0xffffffff, sm, o);
        if (lane == 0) g_rowsum[row] = 1.0f / sm;
    } else {
        int idx = blockIdx.x - 1024;
        int b = idx >> 5, s0 = (idx & 31) * 32;
        int sl = threadIdx.x & 31, mr = threadIdx.x >> 5;
        const float* base = g_E + (size_t)b * MM * SS + s0 + sl;
        float sm = 0.f;
        for (int m = mr; m < MM; m += 8) sm += base[(size_t)m * SS];
        __shared__ float ps[8][33];
        ps[mr][sl] = sm; __syncthreads();
        if (mr == 0) {
            float v = 0.f;
            #pragma unroll
            for (int r = 0; r < 8; r++) v += ps[r][sl];
            g_colsum[b * SS + s0 + sl] = 1.0f / v;
        }
    }
}

// ---------------- exact rescore: 16 parallel accumulators, top-8 output ----------------
__global__ void __launch_bounds__(256) k_rescore(float* __restrict__ mix,
                                                 float* __restrict__ clus) {
    int warp = threadIdx.x >> 5, lane = threadIdx.x & 31;
    int t = blockIdx.x * 8 + warp;
    const float* xp = g_xnw + (size_t)t * DD;
    float xr[24];
    #pragma unroll
    for (int j = 0; j < 24; j++) xr[j] = xp[j * 32 + lane];

    int s_l = (lane < NCAND) ? g_cand[(size_t)t * NCAND + lane] : 0;
    const float* rows[NCAND];
    #pragma unroll
    for (int c = 0; c < NCAND; c++) {
        int s = __shfl_sync(0xffffffff, s_l, c);
        rows[c] = g_phinT + (size_t)s * DD;
    }
    float acc[NCAND];
    #pragma unroll
    for (int c = 0; c < NCAND; c++) acc[c] = 0.f;
    #pragma unroll
    for (int j = 0; j < 24; j++) {
        #pragma unroll
        for (int c = 0; c < NCAND; c++)
            acc[c] = fmaf(xr[j], rows[c][j * 32 + lane], acc[c]);
    }
    float myv = -INFINITY; int myi = 1 << 30;
    #pragma unroll
    for (int c = 0; c < NCAND; c++) {
        float vv = acc[c];
        #pragma unroll
        for (int o = 16; o; o >>= 1) vv += __shfl_xor_sync(0xffffffff, vv, o);
        if (lane == c) { myv = vv; myi = s_l; }
    }
    float lastv = INFINITY; int lasti = -1;
    #pragma unroll
    for (int sel = 0; sel < 8; sel++) {
        float bv = -INFINITY; int bi = 1 << 30;
        bool elig = (myv < lastv) || ((myv == lastv) && (myi > lasti));
        if (elig) { bv = myv; bi = myi; }
        for (int o = 16; o; o >>= 1) {
            float ov = __shfl_xor_sync(0xffffffff, bv, o);
            int   oi = __shfl_xor_sync(0xffffffff, bi, o);
            if ((ov > bv) || ((ov == bv) && (oi < bi))) { bv = ov; bi = oi; }
        }
        lastv = bv; lasti = bi;
        if (lane == 0) {
            mix [(size_t)t * 8 + sel] = bv;
            clus[(size_t)t * 8 + sel] = (float)(bi >> 5);
        }
    }
}

// ---------------- launch ----------------
extern "C" void kernel_launch(void* const* d_in, const int* in_sizes, int n_in,
                              void* d_out, int out_size) {
    const float* x     = (const float*)d_in[0];
    const int*   ca    = (const int*)  d_in[1];
    const float* phi   = (const float*)d_in[2];
    const float* scale = (const float*)d_in[3];
    const float* w1    = (const float*)d_in[4];
    const float* b1    = (const float*)d_in[5];
    const float* w2    = (const float*)d_in[6];
    const float* b2    = (const float*)d_in[7];
    float* out = (float*)d_out;

    const int Y_ELEMS = BB * MM * DD;
    float* mixo = nullptr; float* cluso = nullptr;
    if (out_size >= Y_ELEMS + 2 * TT * KK) {
        mixo  = out + Y_ELEMS;
        cluso = mixo + TT * KK;
    }

    const int SM_ROW  = STAGES * (128*20 + 16*136) * 4;
    const int SM_KMAJ = STAGES * (16*136 + 16*136) * 4;
    cudaFuncSetAttribute(gemm_tc<0>, cudaFuncAttributeMaxDynamicSharedMemorySize, SM_ROW);
    cudaFuncSetAttribute(gemm_tc<1>, cudaFuncAttributeMaxDynamicSharedMemorySize, SM_KMAJ);
    cudaFuncSetAttribute(gemm_tc<2>, cudaFuncAttributeMaxDynamicSharedMemorySize, SM_ROW);
    cudaFuncSetAttribute(gemm_tc<3>, cudaFuncAttributeMaxDynamicSharedMemorySize, SM_ROW);
    cudaFuncSetAttribute(gemm_tc<4>, cudaFuncAttributeMaxDynamicSharedMemorySize, SM_ROW);

    k_colinv<<<32, 256>>>(phi, scale);
    k_phinT<<<dim3(32, 24), 256>>>(phi);
    k_norm_x<<<TT, 256>>>(x);
    k_seg0<<<dim3(NG, 6), 128>>>(ca);
    k_red_mean<<<96, 256>>>();
    k_seg1<<<dim3(NG, 6), 128>>>(ca);
    k_red_mad<<<96, 256>>>();
    k_W<<<1, 1024>>>();
    k_apply<<<TT, 256>>>(ca);

    gemm_tc<0><<<dim3(8, 64), 256, SM_ROW>>>(phi, nullptr, nullptr, ca);  // E (single tf32)

    k_stats<<<1280, 256>>>();
    if (mixo) k_rescore<<<1024, 256>>>(mixo, cluso);

    gemm_tc<1><<<dim3(6, 8, 2*BB), 256, SM_KMAJ>>>(nullptr, nullptr, nullptr, ca); // xs partials
    k_comb_xs<<<8192, 256>>>();
    gemm_tc<2><<<dim3(16, 2, NE), 256, SM_ROW>>>(w1, b1, nullptr, ca);             // h
    gemm_tc<3><<<dim3(6, 2, 2*NE), 256, SM_ROW>>>(w2, nullptr, nullptr, ca);       // ys partials
    k_comb_ys<<<8192, 256>>>(b2);
    gemm_tc<4><<<dim3(6, 8, 2*BB), 256, SM_ROW>>>(nullptr, nullptr, nullptr, ca);  // y partials
    k_comb_y<<<8192, 256>>>(out);
}

// round 17
// speedup vs baseline: 1.0294x; 1.0294x over previous
#include <cuda_runtime.h>
#include <math.h>
#include <stdint.h>

// ---------------- problem constants ----------------
#define BB   8
#define MM   1024
#define DD   768
#define NE   32
#define PE   32
#define KK   8
#define HH   2048
#define SS   1024            // N*P
#define TT   8192            // B*M
#define NG   256             // token groups for segment stats
#define STAGES 3
#define NCAND 16

// ---------------- scratch (device globals; no allocs allowed) ----------------
__device__ float g_xn   [TT * DD];
__device__ float g_xnw  [TT * DD];          // xn * W[ca] (full precision: rescore)
__device__ float g_colinv[SS];
__device__ float g_phinT[SS * DD];          // full-precision phi*colinv, slot-major
__device__ float g_part [NG * NE * DD];
__device__ float g_part2[NG * NE * DD];
__device__ int   g_icnt [NE];
__device__ float g_mean [NE * DD];
__device__ float g_mad  [NE * DD];
__device__ float g_W    [NE * DD];
__device__ float g_E    [TT * SS];          // tf32(exp(logits)) — logits never stored
__device__ int   g_cand [TT * NCAND];
__device__ float g_rowsum[TT];              // 1 / sum_s E
__device__ float g_colsum[BB * SS];         // 1 / sum_m E
__device__ float g_xs [NE * (BB*PE) * DD];  // tf32-rounded
__device__ float g_h  [NE * (BB*PE) * HH];  // tf32-rounded
__device__ float g_ys [NE * (BB*PE) * DD];  // tf32-rounded

__device__ __forceinline__ float gelu_f(float v) {
    return 0.5f * v * (1.0f + erff(v * 0.70710678118654752440f));
}

__device__ __forceinline__ float tf32r(float x) {
    uint32_t r;
    asm("cvt.rna.tf32.f32 %0, %1;" : "=r"(r) : "f"(x));
    return __uint_as_float(r);
}

__device__ __forceinline__ void mma_tf32(float* c, const uint32_t* a,
                                         uint32_t b0, uint32_t b1) {
    asm volatile(
        "mma.sync.aligned.m16n8k8.row.col.f32.tf32.tf32.f32 "
        "{%0,%1,%2,%3}, {%4,%5,%6,%7}, {%8,%9}, {%0,%1,%2,%3};"
        : "+f"(c[0]), "+f"(c[1]), "+f"(c[2]), "+f"(c[3])
        : "r"(a[0]), "r"(a[1]), "r"(a[2]), "r"(a[3]), "r"(b0), "r"(b1));
}

__device__ __forceinline__ void cpasync16(uint32_t dst, const void* src) {
    asm volatile("cp.async.ca.shared.global [%0], [%1], 16;" :: "r"(dst), "l"(src));
}
#define CP_COMMIT()  asm volatile("cp.async.commit_group;" ::: "memory")
#define CP_WAIT1()   asm volatile("cp.async.wait_group 1;"  ::: "memory")

// ---------------- parallel colinv (+ zero cluster counts) ----------------
__global__ void k_colinv(const float* __restrict__ phi, const float* __restrict__ scale) {
    int c = blockIdx.x * 32 + (threadIdx.x & 31);
    int rr = threadIdx.x >> 5;
    if (blockIdx.x == 0 && threadIdx.x < NE) g_icnt[threadIdx.x] = 0;
    float ss = 0.f;
    for (int d = rr; d < DD; d += 8) {
        float v = phi[(size_t)d * SS + c];
        ss += v * v;
    }
    __shared__ float ps[8][33];
    ps[rr][threadIdx.x & 31] = ss;
    __syncthreads();
    if (rr == 0) {
        float v = 0.f;
        #pragma unroll
        for (int r = 0; r < 8; r++) v += ps[r][threadIdx.x & 31];
        g_colinv[c] = scale[0] / fmaxf(sqrtf(v), 1e-12f);
    }
}

// ---------------- phinT = (phi * colinv)^T ----------------
__global__ void k_phinT(const float* __restrict__ phi) {
    __shared__ float tile[32][33];
    int s0 = blockIdx.x * 32, d0 = blockIdx.y * 32;
    int lane = threadIdx.x & 31, w = threadIdx.x >> 5;
    #pragma unroll
    for (int r = w; r < 32; r += 8)
        tile[r][lane] = phi[(size_t)(d0 + r) * SS + s0 + lane];
    __syncthreads();
    #pragma unroll
    for (int r = w; r < 32; r += 8) {
        int s = s0 + r;
        g_phinT[(size_t)s * DD + d0 + lane] = tile[lane][r] * g_colinv[s];
    }
}

// ---------------- token L2 normalize ----------------
__global__ void k_norm_x(const float* __restrict__ x) {
    int t = blockIdx.x, tid = threadIdx.x;
    const float* xr = x + (size_t)t * DD;
    float v0 = xr[tid], v1 = xr[tid + 256], v2 = xr[tid + 512];
    __shared__ float red[256];
    red[tid] = v0*v0 + v1*v1 + v2*v2;
    __syncthreads();
    for (int o = 128; o; o >>= 1) { if (tid < o) red[tid] += red[tid+o]; __syncthreads(); }
    float inv = 1.0f / fmaxf(sqrtf(red[0]), 1e-12f);
    float* o = g_xn + (size_t)t * DD;
    o[tid] = v0*inv; o[tid+256] = v1*inv; o[tid+512] = v2*inv;
}

// ---------------- ACMoE segment stats (deterministic) ----------------
__global__ void k_seg0(const int* __restrict__ ca) {
    __shared__ float acc[NE][129];
    __shared__ int cs[32];
    int tid = threadIdx.x;
    int tg = blockIdx.x, d0 = blockIdx.y * 128;
    #pragma unroll
    for (int c = 0; c < NE; c++) acc[c][tid] = 0.f;
    if (tid < 32) {
        cs[tid] = ca[(size_t)(tg * 32 + tid) * KK];
        if (blockIdx.y == 0) atomicAdd(&g_icnt[cs[tid]], 1);
    }
    __syncthreads();
    const float* base = g_xn + (size_t)(tg * 32) * DD + d0 + tid;
    #pragma unroll 4
    for (int tt = 0; tt < 32; tt++)
        acc[cs[tt]][tid] += base[(size_t)tt * DD];
    __syncthreads();
    #pragma unroll
    for (int c = 0; c < NE; c++)
        g_part[((size_t)tg * NE + c) * DD + d0 + tid] = acc[c][tid];
}

__global__ void k_red_mean() {
    int i = blockIdx.x * 256 + threadIdx.x;
    if (i >= NE * DD) return;
    float s = 0.f;
    #pragma unroll 8
    for (int g = 0; g < NG; g++) s += g_part[(size_t)g * NE * DD + i];
    float cn = (float)g_icnt[i / DD];
    g_mean[i] = cn > 0.f ? s / cn : 0.f;
}

__global__ void k_seg1(const int* __restrict__ ca) {
    __shared__ float acc[NE][129];
    __shared__ float meanS[NE][129];
    __shared__ int cs[32];
    int tid = threadIdx.x;
    int tg = blockIdx.x, d0 = blockIdx.y * 128;
    #pragma unroll
    for (int c = 0; c < NE; c++) {
        acc[c][tid] = 0.f;
        meanS[c][tid] = g_mean[c * DD + d0 + tid];
    }
    if (tid < 32) cs[tid] = ca[(size_t)(tg * 32 + tid) * KK];
    __syncthreads();
    const float* base = g_xn + (size_t)(tg * 32) * DD + d0 + tid;
    #pragma unroll 4
    for (int tt = 0; tt < 32; tt++) {
        int c = cs[tt];
        acc[c][tid] += fabsf(base[(size_t)tt * DD] - meanS[c][tid]);
    }
    __syncthreads();
    #pragma unroll
    for (int c = 0; c < NE; c++)
        g_part2[((size_t)tg * NE + c) * DD + d0 + tid] = acc[c][tid];
}

__global__ void k_red_mad() {
    int i = blockIdx.x * 256 + threadIdx.x;
    if (i >= NE * DD) return;
    float s = 0.f;
    #pragma unroll 8
    for (int g = 0; g < NG; g++) s += g_part2[(size_t)g * NE * DD + i];
    float cn = (float)g_icnt[i / DD];
    g_mad[i] = cn > 0.f ? s / cn : 0.f;
}

__global__ void k_W() {
    __shared__ float red[1024];
    int tid = threadIdx.x;
    float l = 0.f;
    for (int i = tid; i < NE * DD; i += 1024) l += 1.0f / (g_mad[i] + 0.35f);
    red[tid] = l; __syncthreads();
    for (int o = 512; o; o >>= 1) { if (tid < o) red[tid] += red[tid+o]; __syncthreads(); }
    float top = 5.0f * red[0] / (float)(NE * DD);
    __syncthreads();
    float l2 = 0.f;
    for (int i = tid; i < NE * DD; i += 1024) l2 += fminf(1.0f / (g_mad[i] + 0.35f), top);
    red[tid] = l2; __syncthreads();
    for (int o = 512; o; o >>= 1) { if (tid < o) red[tid] += red[tid+o]; __syncthreads(); }
    float m2 = red[0] / (float)(NE * DD);
    __syncthreads();
    for (int i = tid; i < NE * DD; i += 1024)
        g_W[i] = fminf(1.0f / (g_mad[i] + 0.35f), top) / m2;
}

__global__ void k_apply(const int* __restrict__ ca) {
    int t = blockIdx.x, tid = threadIdx.x;
    int c = ca[(size_t)t * KK];
    const float* Wr = g_W + (size_t)c * DD;
    const float* xr = g_xn + (size_t)t * DD;
    float* o = g_xnw + (size_t)t * DD;
    o[tid]       = xr[tid]       * Wr[tid];
    o[tid + 256] = xr[tid + 256] * Wr[tid + 256];
    o[tid + 512] = xr[tid + 512] * Wr[tid + 512];
}

// ---------------- unified tf32 tensor-core GEMM, cp.async 3-stage, BN=128 ----------------
// MODE0: E = tf32(exp(xnw @ (phi*colinv)))  single tf32, E-only output
// MODE1: xs = colinv ⊙ (E^T @ xnw)
// MODE2: h  = tf32(gelu(xs @ w1 + b1))
// MODE3: ys = tf32(h @ w2 + b2)
// MODE4: y  = rowinv ⊙ (E @ ys)
template<int MODE>
__global__ void __launch_bounds__(256, 2) gemm_tc(const float* __restrict__ Bext,
                                                   const float* __restrict__ biasext,
                                                   float* __restrict__ Cext,
                                                   const int* __restrict__ ca) {
    constexpr int KD = (MODE==0)?768 : (MODE==1)?1024 : (MODE==2)?768 : (MODE==3)?2048 : 1024;
    constexpr int BK = 16;
    constexpr int NT = KD / BK;
    constexpr bool AKMAJ = (MODE==1);
    constexpr bool ACVT  = (MODE==0);
    constexpr bool BCVT  = (MODE==1) || (MODE==2) || (MODE==3);
    constexpr bool BSTAGEREG = (MODE==0);
    constexpr bool EPITRUNC = (MODE==1) || (MODE==2) || (MODE==3);
    constexpr int ASZ = AKMAJ ? 16*136 : 128*20;
    constexpr int BSZ = 16*136;

    const int z = blockIdx.z;
    const int i0 = blockIdx.y * 128, j0 = blockIdx.x * 128;
    const int tid = threadIdx.x, lane = tid & 31, warp = tid >> 5;
    const int wmi = warp & 3, wni = warp >> 2;

    extern __shared__ float smem[];
    float* Asm = smem;
    float* Bsm = smem + STAGES * ASZ;
    const uint32_t As_u = (uint32_t)__cvta_generic_to_shared(Asm);
    const uint32_t Bs_u = (uint32_t)__cvta_generic_to_shared(Bsm);

    const float* Aptr = nullptr; int lda = 0;
    const float* Bptr = nullptr; int ldb = 0;
    if constexpr (MODE==0) { Aptr = g_xnw;  lda = 768;  Bptr = Bext; ldb = 1024; }  // raw phi
    if constexpr (MODE==1) { Aptr = g_E + (size_t)z*1024*1024;
                             Bptr = g_xnw + (size_t)z*1024*768; ldb = 768; }
    if constexpr (MODE==2) { Aptr = g_xs + (size_t)z*256*768;   lda = 768;
                             Bptr = Bext + (size_t)z*768*2048;  ldb = 2048; }
    if constexpr (MODE==3) { Aptr = g_h  + (size_t)z*256*2048;  lda = 2048;
                             Bptr = Bext + (size_t)z*2048*768;  ldb = 768; }
    if constexpr (MODE==4) { Aptr = g_E + (size_t)z*1024*1024; lda = 1024;
                             Bptr = g_ys; ldb = 768; }

    const int akk = tid >> 4, ac = (tid & 15) * 8;   // register-staged B indices (MODE0)
    float ci[8];
    if constexpr (BSTAGEREG) {
        #pragma unroll
        for (int q = 0; q < 8; q++) ci[q] = g_colinv[j0 + ac + q];
    }

    float acc[2][8][4];
    #pragma unroll
    for (int mf = 0; mf < 2; mf++)
        #pragma unroll
        for (int nf = 0; nf < 8; nf++)
            #pragma unroll
            for (int q = 0; q < 4; q++) acc[mf][nf][q] = 0.f;

    float4 rb0, rb1;

    auto issue = [&](int it) {
        const int k0 = it * BK;
        const int st = it % STAGES;
        #pragma unroll
        for (int q = 0; q < 2; q++) {
            int c = tid + q * 256;
            if constexpr (AKMAJ) {
                int kk = c >> 5, col = (c & 31) * 4;
                cpasync16(As_u + (uint32_t)(st*ASZ + kk*136 + col) * 4,
                          Aptr + (size_t)(k0 + kk) * 1024 + i0 + col);
            } else {
                int row = c >> 2, col = (c & 3) * 4;
                cpasync16(As_u + (uint32_t)(st*ASZ + row*20 + col) * 4,
                          Aptr + (size_t)(i0 + row) * lda + k0 + col);
            }
        }
        if constexpr (!BSTAGEREG) {
            #pragma unroll
            for (int q = 0; q < 2; q++) {
                int c = tid + q * 256;
                int kk = c >> 5, col = (c & 31) * 4;
                const float* src;
                if constexpr (MODE==4) {
                    int s = k0 + kk;
                    src = Bptr + (size_t)((s >> 5) * 256 + z * 32 + (s & 31)) * 768 + j0 + col;
                } else {
                    src = Bptr + (size_t)(k0 + kk) * ldb + j0 + col;
                }
                cpasync16(Bs_u + (uint32_t)(st*BSZ + kk*136 + col) * 4, src);
            }
        }
    };

    auto loadB0 = [&](int it) {
        const int k0 = it * BK;
        const float* p = Bptr + (size_t)(k0 + akk) * ldb + j0 + ac;
        rb0 = *(const float4*)p;
        rb1 = *(const float4*)(p + 4);
    };
    auto stageB0 = [&](int st) {
        float* d = &Bsm[st*BSZ + akk*136 + ac];
        d[0] = tf32r(rb0.x*ci[0]); d[1] = tf32r(rb0.y*ci[1]);
        d[2] = tf32r(rb0.z*ci[2]); d[3] = tf32r(rb0.w*ci[3]);
        d[4] = tf32r(rb1.x*ci[4]); d[5] = tf32r(rb1.y*ci[5]);
        d[6] = tf32r(rb1.z*ci[6]); d[7] = tf32r(rb1.w*ci[7]);
    };

    auto compute = [&](int st) {
        const float* A = Asm + st * ASZ;
        const float* B = Bsm + st * BSZ;
        #pragma unroll
        for (int ks = 0; ks < 2; ks++) {
            const int kq = ks * 8 + (lane & 3);
            const int rbase = wmi * 32 + (lane >> 2);
            float ar[2][4];
            #pragma unroll
            for (int mf = 0; mf < 2; mf++) {
                if constexpr (AKMAJ) {
                    ar[mf][0] = A[kq*136     + rbase + mf*16];
                    ar[mf][1] = A[kq*136     + rbase + mf*16 + 8];
                    ar[mf][2] = A[(kq+4)*136 + rbase + mf*16];
                    ar[mf][3] = A[(kq+4)*136 + rbase + mf*16 + 8];
                } else {
                    ar[mf][0] = A[(rbase + mf*16    )*20 + kq];
                    ar[mf][1] = A[(rbase + mf*16 + 8)*20 + kq];
                    ar[mf][2] = A[(rbase + mf*16    )*20 + kq + 4];
                    ar[mf][3] = A[(rbase + mf*16 + 8)*20 + kq + 4];
                }
            }
            uint32_t ahi[2][4];
            #pragma unroll
            for (int mf = 0; mf < 2; mf++)
                #pragma unroll
                for (int q = 0; q < 4; q++) {
                    if constexpr (ACVT) ahi[mf][q] = __float_as_uint(tf32r(ar[mf][q]));
                    else                ahi[mf][q] = __float_as_uint(ar[mf][q]);
                }
            #pragma unroll
            for (int nf = 0; nf < 8; nf++) {
                const int nidx = wni * 64 + nf * 8 + (lane >> 2);
                float b0r = B[kq*136 + nidx];
                float b1r = B[(kq+4)*136 + nidx];
                uint32_t bh0, bh1;
                if constexpr (BCVT) {
                    bh0 = __float_as_uint(tf32r(b0r));
                    bh1 = __float_as_uint(tf32r(b1r));
                } else {
                    bh0 = __float_as_uint(b0r);
                    bh1 = __float_as_uint(b1r);
                }
                mma_tf32(acc[0][nf], ahi[0], bh0, bh1);
                mma_tf32(acc[1][nf], ahi[1], bh0, bh1);
            }
        }
    };

    if constexpr (BSTAGEREG) {
        loadB0(0); stageB0(0);
        issue(0); CP_COMMIT();
        loadB0(1); stageB0(1);
        issue(1); CP_COMMIT();
        for (int it = 0; it < NT; it++) {
            const int buf = it % STAGES;
            CP_WAIT1();
            __syncthreads();
            if (it + 2 < NT) loadB0(it + 2);
            compute(buf);
            if (it + 2 < NT) { stageB0((it + 2) % STAGES); issue(it + 2); }
            CP_COMMIT();
        }
    } else {
        issue(0); CP_COMMIT();
        issue(1); CP_COMMIT();
        for (int it = 0; it < NT; it++) {
            const int buf = it % STAGES;
            CP_WAIT1();
            __syncthreads();
            compute(buf);
            if (it + 2 < NT) issue(it + 2);
            CP_COMMIT();
        }
    }

    // epilogue
    #pragma unroll
    for (int mf = 0; mf < 2; mf++) {
        const int r0 = i0 + wmi * 32 + mf * 16 + (lane >> 2);
        float sc0 = 1.f, sc1 = 1.f;
        if constexpr (MODE==1) {
            sc0 = g_colsum[(size_t)z * SS + r0];
            sc1 = g_colsum[(size_t)z * SS + r0 + 8];
        }
        if constexpr (MODE==4) {
            sc0 = g_rowsum[(size_t)z * MM + r0];
            sc1 = g_rowsum[(size_t)z * MM + r0 + 8];
        }
        #pragma unroll
        for (int nf = 0; nf < 8; nf++) {
            const int c = j0 + wni * 64 + nf * 8 + (lane & 3) * 2;
            float v00 = acc[mf][nf][0], v01 = acc[mf][nf][1];
            float v10 = acc[mf][nf][2], v11 = acc[mf][nf][3];
            if constexpr (MODE==1 || MODE==4) {
                v00 *= sc0; v01 *= sc0;
                v10 *= sc1; v11 *= sc1;
            }
            if constexpr (MODE==2) {
                const float* bp = biasext + (size_t)z * 2048 + c;
                float bx = bp[0], by = bp[1];
                v00 = gelu_f(v00 + bx); v01 = gelu_f(v01 + by);
                v10 = gelu_f(v10 + bx); v11 = gelu_f(v11 + by);
            }
            if constexpr (MODE==3) {
                const float* bp = biasext + (size_t)z * 768 + c;
                float bx = bp[0], by = bp[1];
                v00 += bx; v01 += by; v10 += bx; v11 += by;
            }
            if constexpr (EPITRUNC) {
                v00 = tf32r(v00); v01 = tf32r(v01);
                v10 = tf32r(v10); v11 = tf32r(v11);
            }
            float* o0; float* o1;
            if constexpr (MODE==0) {
                size_t off0 = (size_t)r0 * SS + c;
                size_t off1 = off0 + (size_t)8 * SS;
                float2 e0 = {tf32r(__expf(v00)), tf32r(__expf(v01))};
                float2 e1 = {tf32r(__expf(v10)), tf32r(__expf(v11))};
                *(float2*)(g_E + off0) = e0;
                *(float2*)(g_E + off1) = e1;
                continue;
            }
            if constexpr (MODE==1) {
                int rr0 = r0, rr1 = r0 + 8;
                o0 = g_xs + (size_t)((rr0 >> 5) * 256 + z * 32 + (rr0 & 31)) * 768 + c;
                o1 = g_xs + (size_t)((rr1 >> 5) * 256 + z * 32 + (rr1 & 31)) * 768 + c;
            }
            if constexpr (MODE==2) {
                o0 = g_h + (size_t)z*256*2048 + (size_t)r0 * 2048 + c;
                o1 = o0 + (size_t)8 * 2048;
            }
            if constexpr (MODE==3) {
                o0 = g_ys + (size_t)z*256*768 + (size_t)r0 * 768 + c;
                o1 = o0 + (size_t)8 * 768;
            }
            if constexpr (MODE==4) {
                o0 = Cext + (size_t)z*1024*768 + (size_t)r0 * 768 + c;
                o1 = o0 + (size_t)8 * 768;
            }
            float2 w0 = {v00, v01}, w1 = {v10, v11};
            *(float2*)o0 = w0;
            *(float2*)o1 = w1;
        }
    }
}

// ---------------- merged stats: top-16 candidates on E + 1/rowsum + 1/colsum ----------------
__global__ void k_stats() {
    if (blockIdx.x < 1024) {
        int warp = threadIdx.x >> 5, lane = threadIdx.x & 31;
        int row = blockIdx.x * 8 + warp;
        const float* L = g_E + (size_t)row * SS;   // E monotone in logit
        float v[32];
        #pragma unroll
        for (int j = 0; j < 32; j++) v[j] = L[j * 32 + lane];
        float lastv = INFINITY; int lasti = -1;
        #pragma unroll
        for (int sel = 0; sel < NCAND; sel++) {
            float bv = -INFINITY; int bi = 1 << 30;
            #pragma unroll
            for (int j = 0; j < 32; j++) {
                int gi = j * 32 + lane;
                float val = v[j];
                bool elig   = (val < lastv) || ((val == lastv) && (gi > lasti));
                bool better = (val > bv)    || ((val == bv)    && (gi < bi));
                if (elig && better) { bv = val; bi = gi; }
            }
            for (int o = 16; o; o >>= 1) {
                float ov = __shfl_xor_sync(0xffffffff, bv, o);
                int   oi = __shfl_xor_sync(0xffffffff, bi, o);
                if ((ov > bv) || ((ov == bv) && (oi < bi))) { bv = ov; bi = oi; }
            }
            lastv = bv; lasti = bi;
            if (lane == 0) g_cand[(size_t)row * NCAND + sel] = bi;
        }
        float sm = 0.f;
        #pragma unroll
        for (int j = 0; j < 32; j++) sm += v[j];
        for (int o = 16; o; o >>= 1) sm += __shfl_xor_sync(0xffffffff, sm, o);
        if (lane == 0) g_rowsum[row] = 1.0f / sm;
    } else {
        int idx = blockIdx.x - 1024;
        int b = idx >> 5, s0 = (idx & 31) * 32;
        int sl = threadIdx.x & 31, mr = threadIdx.x >> 5;
        const float* base = g_E + (size_t)b * MM * SS + s0 + sl;
        float sm = 0.f;
        for (int m = mr; m < MM; m += 8) sm += base[(size_t)m * SS];
        __shared__ float ps[8][33];
        ps[mr][sl] = sm; __syncthreads();
        if (mr == 0) {
            float v = 0.f;
            #pragma unroll
            for (int r = 0; r < 8; r++) v += ps[r][sl];
            g_colsum[b * SS + s0 + sl] = 1.0f / v;
        }
    }
}

// ---------------- exact rescore: 16 parallel accumulators, top-8 output ----------------
__global__ void __launch_bounds__(256) k_rescore(float* __restrict__ mix,
                                                 float* __restrict__ clus) {
    int warp = threadIdx.x >> 5, lane = threadIdx.x & 31;
    int t = blockIdx.x * 8 + warp;
    const float* xp = g_xnw + (size_t)t * DD;
    float xr[24];
    #pragma unroll
    for (int j = 0; j < 24; j++) xr[j] = xp[j * 32 + lane];

    int s_l = (lane < NCAND) ? g_cand[(size_t)t * NCAND + lane] : 0;
    const float* rows[NCAND];
    #pragma unroll
    for (int c = 0; c < NCAND; c++) {
        int s = __shfl_sync(0xffffffff, s_l, c);
        rows[c] = g_phinT + (size_t)s * DD;
    }
    float acc[NCAND];
    #pragma unroll
    for (int c = 0; c < NCAND; c++) acc[c] = 0.f;
    #pragma unroll
    for (int j = 0; j < 24; j++) {
        #pragma unroll
        for (int c = 0; c < NCAND; c++)
            acc[c] = fmaf(xr[j], rows[c][j * 32 + lane], acc[c]);
    }
    float myv = -INFINITY; int myi = 1 << 30;
    #pragma unroll
    for (int c = 0; c < NCAND; c++) {
        float vv = acc[c];
        #pragma unroll
        for (int o = 16; o; o >>= 1) vv += __shfl_xor_sync(0xffffffff, vv, o);
        if (lane == c) { myv = vv; myi = s_l; }
    }
    float lastv = INFINITY; int lasti = -1;
    #pragma unroll
    for (int sel = 0; sel < 8; sel++) {
        float bv = -INFINITY; int bi = 1 << 30;
        bool elig = (myv < lastv) || ((myv == lastv) && (myi > lasti));
        if (elig) { bv = myv; bi = myi; }
        for (int o = 16; o; o >>= 1) {
            float ov = __shfl_xor_sync(0xffffffff, bv, o);
            int   oi = __shfl_xor_sync(0xffffffff, bi, o);
            if ((ov > bv) || ((ov == bv) && (oi < bi))) { bv = ov; bi = oi; }
        }
        lastv = bv; lasti = bi;
        if (lane == 0) {
            mix [(size_t)t * 8 + sel] = bv;
            clus[(size_t)t * 8 + sel] = (float)(bi >> 5);
        }
    }
}

// ---------------- launch ----------------
extern "C" void kernel_launch(void* const* d_in, const int* in_sizes, int n_in,
                              void* d_out, int out_size) {
    const float* x     = (const float*)d_in[0];
    const int*   ca    = (const int*)  d_in[1];
    const float* phi   = (const float*)d_in[2];
    const float* scale = (const float*)d_in[3];
    const float* w1    = (const float*)d_in[4];
    const float* b1    = (const float*)d_in[5];
    const float* w2    = (const float*)d_in[6];
    const float* b2    = (const float*)d_in[7];
    float* out = (float*)d_out;

    const int Y_ELEMS = BB * MM * DD;
    float* mixo = nullptr; float* cluso = nullptr;
    if (out_size >= Y_ELEMS + 2 * TT * KK) {
        mixo  = out + Y_ELEMS;
        cluso = mixo + TT * KK;
    }

    const int SM_ROW  = STAGES * (128*20 + 16*136) * 4;
    const int SM_KMAJ = STAGES * (16*136 + 16*136) * 4;
    cudaFuncSetAttribute(gemm_tc<0>, cudaFuncAttributeMaxDynamicSharedMemorySize, SM_ROW);
    cudaFuncSetAttribute(gemm_tc<1>, cudaFuncAttributeMaxDynamicSharedMemorySize, SM_KMAJ);
    cudaFuncSetAttribute(gemm_tc<2>, cudaFuncAttributeMaxDynamicSharedMemorySize, SM_ROW);
    cudaFuncSetAttribute(gemm_tc<3>, cudaFuncAttributeMaxDynamicSharedMemorySize, SM_ROW);
    cudaFuncSetAttribute(gemm_tc<4>, cudaFuncAttributeMaxDynamicSharedMemorySize, SM_ROW);

    k_colinv<<<32, 256>>>(phi, scale);
    k_phinT<<<dim3(32, 24), 256>>>(phi);
    k_norm_x<<<TT, 256>>>(x);
    k_seg0<<<dim3(NG, 6), 128>>>(ca);
    k_red_mean<<<96, 256>>>();
    k_seg1<<<dim3(NG, 6), 128>>>(ca);
    k_red_mad<<<96, 256>>>();
    k_W<<<1, 1024>>>();
    k_apply<<<TT, 256>>>(ca);

    gemm_tc<0><<<dim3(8, 64), 256, SM_ROW>>>(phi, nullptr, nullptr, ca);  // E (single tf32)

    k_stats<<<1280, 256>>>();
    if (mixo) k_rescore<<<1024, 256>>>(mixo, cluso);

    gemm_tc<1><<<dim3(6, 8, BB), 256, SM_KMAJ>>>(nullptr, nullptr, nullptr, ca); // xs
    gemm_tc<2><<<dim3(16, 2, NE), 256, SM_ROW>>>(w1, b1, nullptr, ca);           // h
    gemm_tc<3><<<dim3(6, 2, NE), 256, SM_ROW>>>(w2, b2, nullptr, ca);            // ys
    gemm_tc<4><<<dim3(6, 8, BB), 256, SM_ROW>>>(nullptr, nullptr, out, ca);      // y
}